// round 16
// baseline (speedup 1.0000x reference)
#include <cuda_runtime.h>
#include <math.h>

#define TT    512
#define DPOI  256
#define DIN   260
#define DHID  356
#define G3    1536
#define HH    512
#define CL    16          // cluster size
#define DPC   32          // h-dims per CTA
#define HSTR  33          // hist stride (bank-conflict pad)

__device__ float g_x  [TT * DPOI];
__device__ float g_hid[TT * DHID];
__device__ float g_gi [TT * G3];

__device__ __forceinline__ float warp_sum(float v) {
#pragma unroll
    for (int o = 16; o > 0; o >>= 1) v += __shfl_xor_sync(0xffffffffu, v, o);
    return v;
}
__device__ __forceinline__ unsigned smem_u32(const void* p) {
    unsigned a;
    asm("{ .reg .u64 t; cvta.to.shared.u64 t, %1; cvt.u32.u64 %0, t; }" : "=r"(a) : "l"(p));
    return a;
}
__device__ __forceinline__ unsigned mapa_u32(unsigned addr, unsigned rank) {
    unsigned ra;
    asm("mapa.shared::cluster.u32 %0, %1, %2;" : "=r"(ra) : "r"(addr), "r"(rank));
    return ra;
}
__device__ __forceinline__ void st_dsmem(unsigned addr, unsigned rank, float v) {
    unsigned ra = mapa_u32(addr, rank);
    asm volatile("st.shared::cluster.f32 [%0], %1;" :: "r"(ra), "f"(v) : "memory");
}
__device__ __forceinline__ void cluster_sync_() {
    asm volatile("barrier.cluster.arrive.aligned;" ::: "memory");
    asm volatile("barrier.cluster.wait.aligned;"   ::: "memory");
}
__device__ __forceinline__ void mbar_init(unsigned a, unsigned cnt) {
    asm volatile("mbarrier.init.shared.b64 [%0], %1;" :: "r"(a), "r"(cnt) : "memory");
}
__device__ __forceinline__ void mbar_expect(unsigned a, unsigned tx) {
    asm volatile("mbarrier.arrive.expect_tx.shared.b64 _, [%0], %1;" :: "r"(a), "r"(tx) : "memory");
}
__device__ __forceinline__ void mbar_wait(unsigned a, unsigned parity) {
    unsigned done;
    asm volatile(
        "{\n\t.reg .pred p;\n\t"
        "mbarrier.try_wait.parity.acquire.cta.shared::cta.b64 p, [%1], %2;\n\t"
        "selp.b32 %0, 1, 0, p;\n\t}"
        : "=r"(done) : "r"(a), "r"(parity) : "memory");
    if (!done) {
        asm volatile(
            "{\n\t.reg .pred P1;\n\t"
            "W_%=:\n\t"
            "mbarrier.try_wait.parity.acquire.cta.shared::cta.b64 P1, [%0], %1;\n\t"
            "@P1 bra.uni D_%=;\n\t"
            "bra.uni W_%=;\n\t"
            "D_%=:\n\t}"
            :: "r"(a), "r"(parity) : "memory");
    }
}
__device__ __forceinline__ void st_async_f32(unsigned dst, unsigned bar, unsigned rk, float v) {
    unsigned rd, rb;
    asm volatile("mapa.shared::cluster.u32 %0, %1, %2;" : "=r"(rd) : "r"(dst), "r"(rk));
    asm volatile("mapa.shared::cluster.u32 %0, %1, %2;" : "=r"(rb) : "r"(bar), "r"(rk));
    asm volatile("st.async.shared::cluster.mbarrier::complete_tx::bytes.b32 [%0], %1, [%2];"
                 :: "r"(rd), "r"(__float_as_uint(v)), "r"(rb) : "memory");
}
__device__ __forceinline__ void cp16(unsigned dst, const float* src) {
    asm volatile("cp.async.cg.shared.global [%0], [%1], 16;" :: "r"(dst), "l"(src) : "memory");
}
__device__ __forceinline__ void cp_commit() {
    asm volatile("cp.async.commit_group;" ::: "memory");
}
__device__ __forceinline__ float htanh(float x) {
    float y; asm("tanh.approx.f32 %0, %1;" : "=f"(y) : "f"(x)); return y;
}
__device__ __forceinline__ float hsig(float x) {
    return fmaf(htanh(0.5f * x), 0.5f, 0.5f);
}

// ---------------------------------------------------------------- K1a: gather+feat+LN + W1/GELU
#define K1A_W 180
__global__ __launch_bounds__(256) void k1a(
    const int* __restrict__ idx, const float* __restrict__ tf,
    const float* __restrict__ emb, const float* __restrict__ ll,
    const float* __restrict__ lnw, const float* __restrict__ lnb,
    const float* __restrict__ w1, const float* __restrict__ b1)
{
    __shared__ float xs[8 * DIN];
    __shared__ float wbuf[3][20 * K1A_W];
    const int tid = threadIdx.x, warp = tid >> 5, lane = tid & 31;
    const int t0 = blockIdx.x * 8;
    const int ybase = blockIdx.y * 178;
    const int coff  = blockIdx.y * 176;

    {   // one warp per timestep: gather + features + LayerNorm
        const int t = t0 + warp;
        const int pid = idx[t];
        const float4* er = (const float4*)(emb + (size_t)pid * DPOI);
        *(float4*)(xs + warp * DIN + 4 * lane)       = er[lane];
        *(float4*)(xs + warp * DIN + 128 + 4 * lane) = er[lane + 32];
        if (lane == 0) {
            float tc = fminf(fmaxf(tf[t], 0.f), 1.f);
            float s, c; sincosf(6.283185307179586f * tc, &s, &c);
            float f2 = 0.f, f3 = 0.f;
            if (t > 0) {
                float tp = fminf(fmaxf(tf[t - 1], 0.f), 1.f);
                float d = tc - tp;
                float m = d - floorf(d);
                f2 = log1pf(m * 24.f);
                const int ia = idx[t - 1];
                const float R = 0.017453292519943295f;
                float la1 = R * fminf(fmaxf(ll[2 * ia  + 0],  -90.f),  90.f);
                float lo1 = R * fminf(fmaxf(ll[2 * ia  + 1], -180.f), 180.f);
                float la2 = R * fminf(fmaxf(ll[2 * pid + 0],  -90.f),  90.f);
                float lo2 = R * fminf(fmaxf(ll[2 * pid + 1], -180.f), 180.f);
                float sa = sinf((la2 - la1) * 0.5f);
                float sb = sinf((lo2 - lo1) * 0.5f);
                float a = sa * sa + cosf(la1) * cosf(la2) * sb * sb;
                a = fminf(fmaxf(a, 0.f), 1.f);
                float cc = 2.f * atan2f(sqrtf(a), sqrtf(fmaxf(1.f - a, 1e-12f)));
                f3 = log1pf(6371.0088f * cc);
            }
            xs[warp * DIN + 256] = s;  xs[warp * DIN + 257] = c;
            xs[warp * DIN + 258] = f2; xs[warp * DIN + 259] = f3;
        }
        __syncwarp();
        float sm = 0.f, s2 = 0.f;
        for (int k = lane; k < DIN; k += 32) { float v = xs[warp * DIN + k]; sm += v; s2 += v * v; }
        sm = warp_sum(sm); s2 = warp_sum(s2);
        const float mu = sm * (1.f / DIN);
        const float inv = rsqrtf(s2 * (1.f / DIN) - mu * mu + 1e-5f);
        for (int k = lane; k < DIN; k += 32) {
            float v = xs[warp * DIN + k];
            xs[warp * DIN + k] = (v - mu) * inv * __ldg(&lnw[k]) + __ldg(&lnb[k]);
        }
    }
    __syncthreads();

    const bool act = tid < 178;
    const int scol = act ? (ybase - coff) + tid : 0;

#pragma unroll
    for (int pt = 0; pt < 2; pt++) {
        for (int i = tid; i < 900; i += 256) {
            const int row = i / 45, ch = i - row * 45;
            const float* src = w1 + (size_t)(pt * 20 + row) * DHID + coff + ch * 4;
            cp16(smem_u32(&wbuf[pt][row * K1A_W + ch * 4]), src);
        }
        cp_commit();
    }

    float acc[8];
#pragma unroll
    for (int i = 0; i < 8; i++) acc[i] = 0.f;

    for (int t = 0; t < 13; t++) {
        const int buf = t % 3;
        if (t + 2 < 13) {
            const int nb = (t + 2) % 3;
            for (int i = tid; i < 900; i += 256) {
                const int row = i / 45, ch = i - row * 45;
                const float* src = w1 + (size_t)((t + 2) * 20 + row) * DHID + coff + ch * 4;
                cp16(smem_u32(&wbuf[nb][row * K1A_W + ch * 4]), src);
            }
        }
        cp_commit();
        asm volatile("cp.async.wait_group 2;" ::: "memory");
        __syncthreads();
        if (act) {
            const float* wb = &wbuf[buf][0];
            const int k0 = t * 20;
#pragma unroll
            for (int kk = 0; kk < 20; kk++) {
                const float wv = wb[kk * K1A_W + scol];
#pragma unroll
                for (int i = 0; i < 8; i++)
                    acc[i] = fmaf(xs[i * DIN + k0 + kk], wv, acc[i]);
            }
        }
        __syncthreads();
    }
    if (act) {
        const int h = ybase + tid;
        const float bb = __ldg(&b1[h]);
#pragma unroll
        for (int i = 0; i < 8; i++) {
            float v = acc[i] + bb;
            g_hid[(t0 + i) * DHID + h] = 0.5f * v * (1.f + erff(v * 0.7071067811865475f));
        }
    }
}

// ---------------------------------------------------------------- K1b: x = hid @ W2 + b2
__global__ __launch_bounds__(256) void k1b(
    const float* __restrict__ w2, const float* __restrict__ b2)
{
    __shared__ float hb[8 * DHID];
    __shared__ float w2buf[3][16 * 128];
    const int tid = threadIdx.x;
    const int t0 = blockIdx.x * 8;
    const int obase = blockIdx.y * 128;

    for (int i = tid; i < 8 * DHID; i += 256) hb[i] = g_hid[t0 * DHID + i];

    const bool act = tid < 128;
    const int NT = 23;

#pragma unroll
    for (int pt = 0; pt < 2; pt++) {
        for (int i = tid; i < 512; i += 256) {
            const int row = i >> 5, ch = i & 31;
            const float* src = w2 + (size_t)(pt * 16 + row) * DPOI + obase + ch * 4;
            cp16(smem_u32(&w2buf[pt][row * 128 + ch * 4]), src);
        }
        cp_commit();
    }
    __syncthreads();

    float acc[8];
#pragma unroll
    for (int i = 0; i < 8; i++) acc[i] = 0.f;

    for (int t = 0; t < NT; t++) {
        const int buf = t % 3;
        if (t + 2 < NT) {
            const int tn = t + 2, nb = tn % 3;
            const int rows = (tn * 16 + 16 <= DHID) ? 16 : (DHID - tn * 16);
            for (int i = tid; i < rows * 32; i += 256) {
                const int row = i >> 5, ch = i & 31;
                const float* src = w2 + (size_t)(tn * 16 + row) * DPOI + obase + ch * 4;
                cp16(smem_u32(&w2buf[nb][row * 128 + ch * 4]), src);
            }
        }
        cp_commit();
        asm volatile("cp.async.wait_group 2;" ::: "memory");
        __syncthreads();
        if (act) {
            const int k0 = t * 16;
            const int kmax = (k0 + 16 <= DHID) ? 16 : (DHID - k0);
            const float* wb = &w2buf[buf][0];
            for (int kk = 0; kk < kmax; kk++) {
                const float wv = wb[kk * 128 + tid];
#pragma unroll
                for (int i = 0; i < 8; i++)
                    acc[i] = fmaf(hb[i * DHID + k0 + kk], wv, acc[i]);
            }
        }
        __syncthreads();
    }
    if (act) {
        const int o = obase + tid;
        const float bo = __ldg(&b2[o]);
#pragma unroll
        for (int i = 0; i < 8; i++) g_x[(t0 + i) * DPOI + o] = acc[i] + bo;
    }
}

// ---------------------------------------------------------------- K2: gi = x @ W_ih^T + bias
__global__ __launch_bounds__(256) void k2_gi(
    const float* __restrict__ wih, const float* __restrict__ bih,
    const float* __restrict__ bhh)
{
    __shared__ float xsm[16 * DPOI];
    __shared__ float wsmT[16 * 257];
    const int tid = threadIdx.x;
    const int t0 = blockIdx.x * 16;
    const int g0 = blockIdx.y * 256;

    for (int i = tid; i < 1024; i += 256)
        *(float4*)(xsm + 4 * i) = *(const float4*)(g_x + t0 * DPOI + 4 * i);

    float acc[16];
#pragma unroll
    for (int i = 0; i < 16; i++) acc[i] = 0.f;

    for (int k0 = 0; k0 < DPOI; k0 += 16) {
        __syncthreads();
        for (int i = tid; i < 4096; i += 256) {
            const int kk = i & 15, g = i >> 4;
            wsmT[kk * 257 + g] = wih[(size_t)(g0 + g) * DPOI + k0 + kk];
        }
        __syncthreads();
#pragma unroll
        for (int k4 = 0; k4 < 4; k4++) {
#pragma unroll
            for (int half = 0; half < 2; half++) {
                float4 xv[8];
#pragma unroll
                for (int i = 0; i < 8; i++)
                    xv[i] = *(const float4*)(xsm + (half * 8 + i) * DPOI + k0 + 4 * k4);
#pragma unroll
                for (int c = 0; c < 4; c++) {
                    const float w = wsmT[(4 * k4 + c) * 257 + tid];
#pragma unroll
                    for (int i = 0; i < 8; i++) {
                        float xk = (c == 0) ? xv[i].x : (c == 1) ? xv[i].y : (c == 2) ? xv[i].z : xv[i].w;
                        acc[half * 8 + i] = fmaf(xk, w, acc[half * 8 + i]);
                    }
                }
            }
        }
    }
    const int g = g0 + tid;
    float b = __ldg(&bih[g]);
    if (g < 2 * HH) b += __ldg(&bhh[g]);   // fold r,z hidden biases
#pragma unroll
    for (int i = 0; i < 16; i++) g_gi[(size_t)(t0 + i) * G3 + g] = acc[i] + b;
}

// ---------------------------------------------------------------- K3: GRU scan + fused epilogue
// R13/R15 structure with ONE change: the gate phase is split across TWO warps
// (warp 0 -> dims 0-15, warp 1 -> dims 16-31), each with its OWN gi prefetch
// stream (cp16 x12 lanes, own commit/wait per step) so cp.async visibility
// stays warp-local. Broadcast: each lane ships its dim to 8 ranks.
__global__ void __launch_bounds__(512, 1) __cluster_dims__(CL, 1, 1)
k3_gru(const float* __restrict__ whh, const float* __restrict__ bhh,
       const float* __restrict__ gq, const float* __restrict__ loglam,
       float* __restrict__ out, int out_size)
{
    extern __shared__ float sm[];
    float* hbuf = sm;                    // 4*512
    float* hist = sm + 2048;             // 512*33
    float* part = sm + 18944;            // 16*512
    float* attn = sm + 27136;            // 512
    float* scp  = sm + 27648;            // 512
    float* ghs  = sm + 28160;            // 96
    float* bsn  = sm + 28256;            // 32
    float* qv   = sm + 28288;            // 32
    float* red  = sm + 28320;            // 16
    const unsigned mb = smem_u32(sm + 28336);   // 4 mbarriers
    float* gring = sm + 28352;           // 8*96 gi ring
#define MB_FULL(s) (mb + (unsigned)((s) * 8))

    const int tid = threadIdx.x, warp = tid >> 5, lane = tid & 31;
    unsigned c; asm("mov.u32 %0, %%cluster_ctarank;" : "=r"(c));

    if (tid == 0) {
#pragma unroll
        for (int s = 0; s < 4; s++) mbar_init(MB_FULL(s), 1);
    }
    for (int i = tid; i < 2048; i += 512) hbuf[i] = 0.f;
    if (tid < 32) {
        qv[tid]  = gq[(int)c * DPC + tid] * rsqrtf((float)HH);
        bsn[tid] = bhh[2 * HH + (int)c * DPC + tid];
    }

    // resident rows: warp w, r=0..5 -> gate (r>>1), dim 2w + (r&1)
    unsigned long long w[6][8];
#pragma unroll
    for (int r = 0; r < 6; r++) {
        const int grow = (r >> 1) * HH + (int)c * DPC + 2 * warp + (r & 1);
        const unsigned long long* wp = (const unsigned long long*)(whh + (size_t)grow * HH);
#pragma unroll
        for (int j = 0; j < 8; j++) w[r][j] = wp[lane + 32 * j];
    }

    // per-gate-warp gi prefetch: warp wg (<2) covers dims [16wg,16wg+16);
    // lane l<12: gate = l>>2, chunk = l&3 -> one cp16 per step.
    const unsigned gring_base = smem_u32(gring);
    const int pf_gate = lane >> 2, pf_chunk = lane & 3;
    const float* pf_src0 = g_gi + pf_gate * HH + (int)c * DPC + 16 * warp + pf_chunk * 4;
    const unsigned pf_dst0 = gring_base +
        (unsigned)((pf_gate * 32 + 16 * warp + pf_chunk * 4) * 4);
    const bool is_gw = (warp < 2);
    const bool pf_on = (is_gw && lane < 12);

    __syncthreads();
    cluster_sync_();   // mbarriers + zeroed hbuf visible before any st.async

    const unsigned hb_base = smem_u32(hbuf);

    // prologue: each gate warp prefetches its half of gi for steps 0..3
    if (is_gw) {
#pragma unroll
        for (int pt = 0; pt < 4; pt++) {
            if (pf_on) cp16(pf_dst0 + (unsigned)(pt * 96 * 4), pf_src0 + (size_t)pt * G3);
            cp_commit();
        }
    }

    for (int t = 0; t < TT; t++) {
        const int wsl = t & 3, psl = (t + 3) & 3;
        if (t > 0) mbar_wait(MB_FULL(psl), (unsigned)((t - 1) >> 2) & 1u);
        if (tid == 0) mbar_expect(MB_FULL(wsl), 2048u);

        // gate warps: prefetch own half of gi for step t+4 into slot (t+4)&7
        if (is_gw) {
            const int tn = (t + 4 < TT) ? t + 4 : TT - 1;
            if (pf_on) cp16(pf_dst0 + (unsigned)(((t + 4) & 7) * 96 * 4),
                            pf_src0 + (size_t)tn * G3);
            cp_commit();
        }

        // 6 dots over h(t-1)
        unsigned long long acc[6];
#pragma unroll
        for (int r = 0; r < 6; r++) acc[r] = 0ull;
        const unsigned long long* h2 = (const unsigned long long*)(hbuf + psl * 512);
#pragma unroll
        for (int j = 0; j < 8; j++) {
            const unsigned long long hv = h2[lane + 32 * j];
#pragma unroll
            for (int r = 0; r < 6; r++)
                asm("fma.rn.f32x2 %0, %1, %2, %0;" : "+l"(acc[r]) : "l"(w[r][j]), "l"(hv));
        }
        // paired reduction: even lane -> dim 2w, odd lane -> dim 2w+1
#pragma unroll
        for (int g = 0; g < 3; g++) {
            float lo, hi;
            asm("mov.b64 {%0, %1}, %2;" : "=f"(lo), "=f"(hi) : "l"(acc[2 * g]));
            const float ae = lo + hi;
            asm("mov.b64 {%0, %1}, %2;" : "=f"(lo), "=f"(hi) : "l"(acc[2 * g + 1]));
            const float ao = lo + hi;
            const float zv = (lane & 1) ? ae : ao;
            float v = ((lane & 1) ? ao : ae) + __shfl_xor_sync(0xffffffffu, zv, 1);
#pragma unroll
            for (int o = 2; o <= 16; o <<= 1) v += __shfl_xor_sync(0xffffffffu, v, o);
            if (lane < 2) ghs[g * 32 + 2 * warp + lane] = v;
        }
        __syncthreads();

        // TWO gate warps: HW-tanh gates + 8-rank broadcast per lane
        if (is_gw) {
            asm volatile("cp.async.wait_group 4;" ::: "memory");
            __syncwarp();
            const int m = 16 * warp + (lane & 15);
            const float* gslot = gring + (t & 7) * 96;
            const float rg = hsig(gslot[m]      + ghs[m]);
            const float zg = hsig(gslot[32 + m] + ghs[32 + m]);
            const float ng = htanh(gslot[64 + m] + rg * (ghs[64 + m] + bsn[m]));
            const float hn = (1.f - zg) * ng + zg * hbuf[psl * 512 + (int)c * DPC + m];
            if (lane < 16) hist[t * HSTR + m] = hn;
            const unsigned dst = hb_base + (unsigned)((wsl * 512 + (int)c * DPC + m) * 4);
            const unsigned bar = MB_FULL(wsl);
            const unsigned rk0 = (unsigned)(lane >> 4) * 8;
#pragma unroll
            for (unsigned k = 0; k < 8; k++) st_async_f32(dst, bar, rk0 + k, hn);
        }
    }
    mbar_wait(MB_FULL(3), 1u);   // drain final slot
    __syncthreads();

    // ---- fused epilogue ----
    {   // partial scores: thread tid = timestep tid over this CTA's 32 dims
        float a = 0.f;
#pragma unroll 8
        for (int m = 0; m < 32; m++) a = fmaf(hist[tid * HSTR + m], qv[m], a);
        scp[tid] = a;
    }
    __syncthreads();
    {   // ship partials to rank 0
        const unsigned paddr = smem_u32(part) + (unsigned)(((int)c * 512 + tid) * 4);
        st_dsmem(paddr, 0u, scp[tid]);
    }
    cluster_sync_();

    if (c == 0) {
        const float lam = fmaxf(expf(loglam[0]), 1e-4f);
        float s = 0.f;
#pragma unroll
        for (int cc = 0; cc < CL; cc++) s += part[cc * 512 + tid];
        s -= lam * (float)(TT - 1 - tid);

        float m = s;
#pragma unroll
        for (int o = 16; o > 0; o >>= 1) m = fmaxf(m, __shfl_xor_sync(0xffffffffu, m, o));
        if (lane == 0) red[warp] = m;
        __syncthreads();
        if (tid < 16) {
            float x = red[tid];
#pragma unroll
            for (int o = 8; o > 0; o >>= 1) x = fmaxf(x, __shfl_xor_sync(0xffffu, x, o));
            if (tid == 0) red[0] = x;
        }
        __syncthreads();
        const float mx = red[0];
        const float e = expf(s - mx);
        float ssum = warp_sum(e);
        __syncthreads();
        if (lane == 0) red[warp] = ssum;
        __syncthreads();
        if (tid < 16) {
            float x = red[tid];
#pragma unroll
            for (int o = 8; o > 0; o >>= 1) x += __shfl_xor_sync(0xffffu, x, o);
            if (tid == 0) red[0] = x;
        }
        __syncthreads();
        const float a = e / red[0];
        attn[tid] = a;
        if (out_size >= 1024) out[HH + tid] = a;
        const unsigned aaddr = smem_u32(attn) + (unsigned)(tid * 4);
        for (unsigned rk = 1; rk < CL; rk++) st_dsmem(aaddr, rk, a);
    }
    cluster_sync_();

    {   // summary: warp g sums timesteps [32g,32g+32), lane = dim
        const int dd = tid & 31, g = tid >> 5;
        float a = 0.f;
#pragma unroll 4
        for (int i = 0; i < 32; i++) {
            const int t = g * 32 + i;
            a = fmaf(attn[t], hist[t * HSTR + dd], a);
        }
        scp[g * 32 + dd] = a;
    }
    __syncthreads();
    if (tid < 32) {
        float s = 0.f;
#pragma unroll
        for (int g = 0; g < 16; g++) s += scp[g * 32 + tid];
        const int o = (int)c * DPC + tid;
        if (o < out_size) out[o] = s;
    }
    cluster_sync_();
}

// ---------------------------------------------------------------- launch
extern "C" void kernel_launch(void* const* d_in, const int* in_sizes, int n_in,
                              void* d_out, int out_size) {
    const int*   idx = (const int*)  d_in[0];
    const float* tf  = (const float*)d_in[1];
    const float* emb = (const float*)d_in[2];
    const float* ll  = (const float*)d_in[3];
    const float* lnw = (const float*)d_in[4];
    const float* lnb = (const float*)d_in[5];
    const float* w1  = (const float*)d_in[6];
    const float* b1  = (const float*)d_in[7];
    const float* w2  = (const float*)d_in[8];
    const float* b2  = (const float*)d_in[9];
    const float* wih = (const float*)d_in[10];
    const float* whh = (const float*)d_in[11];
    const float* bih = (const float*)d_in[12];
    const float* bhh = (const float*)d_in[13];
    const float* q   = (const float*)d_in[14];
    const float* llm = (const float*)d_in[15];
    float* out = (float*)d_out;

    const int k3_smem = 29120 * (int)sizeof(float);   // 116480 B

    static int attr_done = 0;
    if (!attr_done) {
        cudaFuncSetAttribute(k3_gru, cudaFuncAttributeNonPortableClusterSizeAllowed, 1);
        cudaFuncSetAttribute(k3_gru, cudaFuncAttributeMaxDynamicSharedMemorySize, k3_smem);
        attr_done = 1;
    }

    k1a<<<dim3(64, 2), 256>>>(idx, tf, emb, ll, lnw, lnb, w1, b1);
    k1b<<<dim3(64, 2), 256>>>(w2, b2);
    k2_gi<<<dim3(32, 6), 256>>>(wih, bih, bhh);
    k3_gru<<<CL, 512, k3_smem>>>(whh, bhh, q, llm, out, out_size);
}

// round 17
// speedup vs baseline: 1.0922x; 1.0922x over previous
#include <cuda_runtime.h>
#include <math.h>

#define TT    512
#define DPOI  256
#define DIN   260
#define DHID  356
#define G3    1536
#define HH    512
#define CL    16          // cluster size
#define DPC   32          // h-dims per CTA
#define HSTR  33          // hist stride (bank-conflict pad)

__device__ float g_x  [TT * DPOI];
__device__ float g_hid[TT * DHID];
__device__ float g_gi [TT * G3];

__device__ __forceinline__ float warp_sum(float v) {
#pragma unroll
    for (int o = 16; o > 0; o >>= 1) v += __shfl_xor_sync(0xffffffffu, v, o);
    return v;
}
__device__ __forceinline__ unsigned smem_u32(const void* p) {
    unsigned a;
    asm("{ .reg .u64 t; cvta.to.shared.u64 t, %1; cvt.u32.u64 %0, t; }" : "=r"(a) : "l"(p));
    return a;
}
__device__ __forceinline__ unsigned mapa_u32(unsigned addr, unsigned rank) {
    unsigned ra;
    asm("mapa.shared::cluster.u32 %0, %1, %2;" : "=r"(ra) : "r"(addr), "r"(rank));
    return ra;
}
__device__ __forceinline__ void st_dsmem(unsigned addr, unsigned rank, float v) {
    unsigned ra = mapa_u32(addr, rank);
    asm volatile("st.shared::cluster.f32 [%0], %1;" :: "r"(ra), "f"(v) : "memory");
}
__device__ __forceinline__ void cluster_sync_() {
    asm volatile("barrier.cluster.arrive.aligned;" ::: "memory");
    asm volatile("barrier.cluster.wait.aligned;"   ::: "memory");
}
__device__ __forceinline__ void mbar_init(unsigned a, unsigned cnt) {
    asm volatile("mbarrier.init.shared.b64 [%0], %1;" :: "r"(a), "r"(cnt) : "memory");
}
__device__ __forceinline__ void mbar_expect(unsigned a, unsigned tx) {
    asm volatile("mbarrier.arrive.expect_tx.shared.b64 _, [%0], %1;" :: "r"(a), "r"(tx) : "memory");
}
__device__ __forceinline__ void mbar_wait(unsigned a, unsigned parity) {
    unsigned done;
    asm volatile(
        "{\n\t.reg .pred p;\n\t"
        "mbarrier.try_wait.parity.acquire.cta.shared::cta.b64 p, [%1], %2;\n\t"
        "selp.b32 %0, 1, 0, p;\n\t}"
        : "=r"(done) : "r"(a), "r"(parity) : "memory");
    if (!done) {
        asm volatile(
            "{\n\t.reg .pred P1;\n\t"
            "W_%=:\n\t"
            "mbarrier.try_wait.parity.acquire.cta.shared::cta.b64 P1, [%0], %1;\n\t"
            "@P1 bra.uni D_%=;\n\t"
            "bra.uni W_%=;\n\t"
            "D_%=:\n\t}"
            :: "r"(a), "r"(parity) : "memory");
    }
}
__device__ __forceinline__ void st_async_f32(unsigned dst, unsigned bar, unsigned rk, float v) {
    unsigned rd, rb;
    asm volatile("mapa.shared::cluster.u32 %0, %1, %2;" : "=r"(rd) : "r"(dst), "r"(rk));
    asm volatile("mapa.shared::cluster.u32 %0, %1, %2;" : "=r"(rb) : "r"(bar), "r"(rk));
    asm volatile("st.async.shared::cluster.mbarrier::complete_tx::bytes.b32 [%0], %1, [%2];"
                 :: "r"(rd), "r"(__float_as_uint(v)), "r"(rb) : "memory");
}
__device__ __forceinline__ void cp16(unsigned dst, const float* src) {
    asm volatile("cp.async.cg.shared.global [%0], [%1], 16;" :: "r"(dst), "l"(src) : "memory");
}
__device__ __forceinline__ void cp_commit() {
    asm volatile("cp.async.commit_group;" ::: "memory");
}
__device__ __forceinline__ float htanh(float x) {
    float y; asm("tanh.approx.f32 %0, %1;" : "=f"(y) : "f"(x)); return y;
}
__device__ __forceinline__ float hsig(float x) {
    return fmaf(htanh(0.5f * x), 0.5f, 0.5f);
}

// ---------------------------------------------------------------- K1a: gather+feat+LN + W1/GELU
#define K1A_W 180
__global__ __launch_bounds__(256) void k1a(
    const int* __restrict__ idx, const float* __restrict__ tf,
    const float* __restrict__ emb, const float* __restrict__ ll,
    const float* __restrict__ lnw, const float* __restrict__ lnb,
    const float* __restrict__ w1, const float* __restrict__ b1)
{
    __shared__ float xs[8 * DIN];
    __shared__ float wbuf[3][20 * K1A_W];
    const int tid = threadIdx.x, warp = tid >> 5, lane = tid & 31;
    const int t0 = blockIdx.x * 8;
    const int ybase = blockIdx.y * 178;
    const int coff  = blockIdx.y * 176;

    {   // one warp per timestep: gather + features + LayerNorm
        const int t = t0 + warp;
        const int pid = idx[t];
        const float4* er = (const float4*)(emb + (size_t)pid * DPOI);
        *(float4*)(xs + warp * DIN + 4 * lane)       = er[lane];
        *(float4*)(xs + warp * DIN + 128 + 4 * lane) = er[lane + 32];
        if (lane == 0) {
            float tc = fminf(fmaxf(tf[t], 0.f), 1.f);
            float s, c; sincosf(6.283185307179586f * tc, &s, &c);
            float f2 = 0.f, f3 = 0.f;
            if (t > 0) {
                float tp = fminf(fmaxf(tf[t - 1], 0.f), 1.f);
                float d = tc - tp;
                float m = d - floorf(d);
                f2 = log1pf(m * 24.f);
                const int ia = idx[t - 1];
                const float R = 0.017453292519943295f;
                float la1 = R * fminf(fmaxf(ll[2 * ia  + 0],  -90.f),  90.f);
                float lo1 = R * fminf(fmaxf(ll[2 * ia  + 1], -180.f), 180.f);
                float la2 = R * fminf(fmaxf(ll[2 * pid + 0],  -90.f),  90.f);
                float lo2 = R * fminf(fmaxf(ll[2 * pid + 1], -180.f), 180.f);
                float sa = sinf((la2 - la1) * 0.5f);
                float sb = sinf((lo2 - lo1) * 0.5f);
                float a = sa * sa + cosf(la1) * cosf(la2) * sb * sb;
                a = fminf(fmaxf(a, 0.f), 1.f);
                float cc = 2.f * atan2f(sqrtf(a), sqrtf(fmaxf(1.f - a, 1e-12f)));
                f3 = log1pf(6371.0088f * cc);
            }
            xs[warp * DIN + 256] = s;  xs[warp * DIN + 257] = c;
            xs[warp * DIN + 258] = f2; xs[warp * DIN + 259] = f3;
        }
        __syncwarp();
        float sm = 0.f, s2 = 0.f;
        for (int k = lane; k < DIN; k += 32) { float v = xs[warp * DIN + k]; sm += v; s2 += v * v; }
        sm = warp_sum(sm); s2 = warp_sum(s2);
        const float mu = sm * (1.f / DIN);
        const float inv = rsqrtf(s2 * (1.f / DIN) - mu * mu + 1e-5f);
        for (int k = lane; k < DIN; k += 32) {
            float v = xs[warp * DIN + k];
            xs[warp * DIN + k] = (v - mu) * inv * __ldg(&lnw[k]) + __ldg(&lnb[k]);
        }
    }
    __syncthreads();

    const bool act = tid < 178;
    const int scol = act ? (ybase - coff) + tid : 0;

#pragma unroll
    for (int pt = 0; pt < 2; pt++) {
        for (int i = tid; i < 900; i += 256) {
            const int row = i / 45, ch = i - row * 45;
            const float* src = w1 + (size_t)(pt * 20 + row) * DHID + coff + ch * 4;
            cp16(smem_u32(&wbuf[pt][row * K1A_W + ch * 4]), src);
        }
        cp_commit();
    }

    float acc[8];
#pragma unroll
    for (int i = 0; i < 8; i++) acc[i] = 0.f;

    for (int t = 0; t < 13; t++) {
        const int buf = t % 3;
        if (t + 2 < 13) {
            const int nb = (t + 2) % 3;
            for (int i = tid; i < 900; i += 256) {
                const int row = i / 45, ch = i - row * 45;
                const float* src = w1 + (size_t)((t + 2) * 20 + row) * DHID + coff + ch * 4;
                cp16(smem_u32(&wbuf[nb][row * K1A_W + ch * 4]), src);
            }
        }
        cp_commit();
        asm volatile("cp.async.wait_group 2;" ::: "memory");
        __syncthreads();
        if (act) {
            const float* wb = &wbuf[buf][0];
            const int k0 = t * 20;
#pragma unroll
            for (int kk = 0; kk < 20; kk++) {
                const float wv = wb[kk * K1A_W + scol];
#pragma unroll
                for (int i = 0; i < 8; i++)
                    acc[i] = fmaf(xs[i * DIN + k0 + kk], wv, acc[i]);
            }
        }
        __syncthreads();
    }
    if (act) {
        const int h = ybase + tid;
        const float bb = __ldg(&b1[h]);
#pragma unroll
        for (int i = 0; i < 8; i++) {
            float v = acc[i] + bb;
            g_hid[(t0 + i) * DHID + h] = 0.5f * v * (1.f + erff(v * 0.7071067811865475f));
        }
    }
}

// ---------------------------------------------------------------- K1b: x = hid @ W2 + b2
__global__ __launch_bounds__(256) void k1b(
    const float* __restrict__ w2, const float* __restrict__ b2)
{
    __shared__ float hb[8 * DHID];
    __shared__ float w2buf[3][16 * 128];
    const int tid = threadIdx.x;
    const int t0 = blockIdx.x * 8;
    const int obase = blockIdx.y * 128;

    for (int i = tid; i < 8 * DHID; i += 256) hb[i] = g_hid[t0 * DHID + i];

    const bool act = tid < 128;
    const int NT = 23;

#pragma unroll
    for (int pt = 0; pt < 2; pt++) {
        for (int i = tid; i < 512; i += 256) {
            const int row = i >> 5, ch = i & 31;
            const float* src = w2 + (size_t)(pt * 16 + row) * DPOI + obase + ch * 4;
            cp16(smem_u32(&w2buf[pt][row * 128 + ch * 4]), src);
        }
        cp_commit();
    }
    __syncthreads();

    float acc[8];
#pragma unroll
    for (int i = 0; i < 8; i++) acc[i] = 0.f;

    for (int t = 0; t < NT; t++) {
        const int buf = t % 3;
        if (t + 2 < NT) {
            const int tn = t + 2, nb = tn % 3;
            const int rows = (tn * 16 + 16 <= DHID) ? 16 : (DHID - tn * 16);
            for (int i = tid; i < rows * 32; i += 256) {
                const int row = i >> 5, ch = i & 31;
                const float* src = w2 + (size_t)(tn * 16 + row) * DPOI + obase + ch * 4;
                cp16(smem_u32(&w2buf[nb][row * 128 + ch * 4]), src);
            }
        }
        cp_commit();
        asm volatile("cp.async.wait_group 2;" ::: "memory");
        __syncthreads();
        if (act) {
            const int k0 = t * 16;
            const int kmax = (k0 + 16 <= DHID) ? 16 : (DHID - k0);
            const float* wb = &w2buf[buf][0];
            for (int kk = 0; kk < kmax; kk++) {
                const float wv = wb[kk * 128 + tid];
#pragma unroll
                for (int i = 0; i < 8; i++)
                    acc[i] = fmaf(hb[i * DHID + k0 + kk], wv, acc[i]);
            }
        }
        __syncthreads();
    }
    if (act) {
        const int o = obase + tid;
        const float bo = __ldg(&b2[o]);
#pragma unroll
        for (int i = 0; i < 8; i++) g_x[(t0 + i) * DPOI + o] = acc[i] + bo;
    }
}

// ---------------------------------------------------------------- K2: gi = x @ W_ih^T + bias
__global__ __launch_bounds__(256) void k2_gi(
    const float* __restrict__ wih, const float* __restrict__ bih,
    const float* __restrict__ bhh)
{
    __shared__ float xsm[16 * DPOI];
    __shared__ float wsmT[16 * 257];
    const int tid = threadIdx.x;
    const int t0 = blockIdx.x * 16;
    const int g0 = blockIdx.y * 256;

    for (int i = tid; i < 1024; i += 256)
        *(float4*)(xsm + 4 * i) = *(const float4*)(g_x + t0 * DPOI + 4 * i);

    float acc[16];
#pragma unroll
    for (int i = 0; i < 16; i++) acc[i] = 0.f;

    for (int k0 = 0; k0 < DPOI; k0 += 16) {
        __syncthreads();
        for (int i = tid; i < 4096; i += 256) {
            const int kk = i & 15, g = i >> 4;
            wsmT[kk * 257 + g] = wih[(size_t)(g0 + g) * DPOI + k0 + kk];
        }
        __syncthreads();
#pragma unroll
        for (int k4 = 0; k4 < 4; k4++) {
#pragma unroll
            for (int half = 0; half < 2; half++) {
                float4 xv[8];
#pragma unroll
                for (int i = 0; i < 8; i++)
                    xv[i] = *(const float4*)(xsm + (half * 8 + i) * DPOI + k0 + 4 * k4);
#pragma unroll
                for (int c = 0; c < 4; c++) {
                    const float w = wsmT[(4 * k4 + c) * 257 + tid];
#pragma unroll
                    for (int i = 0; i < 8; i++) {
                        float xk = (c == 0) ? xv[i].x : (c == 1) ? xv[i].y : (c == 2) ? xv[i].z : xv[i].w;
                        acc[half * 8 + i] = fmaf(xk, w, acc[half * 8 + i]);
                    }
                }
            }
        }
    }
    const int g = g0 + tid;
    float b = __ldg(&bih[g]);
    if (g < 2 * HH) b += __ldg(&bhh[g]);   // fold r,z hidden biases
#pragma unroll
    for (int i = 0; i < 16; i++) g_gi[(size_t)(t0 + i) * G3 + g] = acc[i] + b;
}

// ---------------------------------------------------------------- K3: GRU scan + fused epilogue
// R15 structure; ONLY the dot/reduce geometry changed: 16 lanes per row
// (half h = lane>>4 -> dim 2w+h; pass p = gate p; lane covers K-pairs
// (lane&15)+16j). Reduction = 4 shfl levels over 16 lanes instead of 5+select.
__global__ void __launch_bounds__(512, 1) __cluster_dims__(CL, 1, 1)
k3_gru(const float* __restrict__ whh, const float* __restrict__ bhh,
       const float* __restrict__ gq, const float* __restrict__ loglam,
       float* __restrict__ out, int out_size)
{
    extern __shared__ float sm[];
    float* hbuf = sm;                    // 4*512
    float* hist = sm + 2048;             // 512*33
    float* part = sm + 18944;            // 16*512
    float* attn = sm + 27136;            // 512
    float* scp  = sm + 27648;            // 512
    float* ghs  = sm + 28160;            // 96
    float* bsn  = sm + 28256;            // 32
    float* qv   = sm + 28288;            // 32
    float* red  = sm + 28320;            // 16
    const unsigned mb = smem_u32(sm + 28336);   // 4 mbarriers
    float* gring = sm + 28352;           // 8*96 gi ring
#define MB_FULL(s) (mb + (unsigned)((s) * 8))

    const int tid = threadIdx.x, warp = tid >> 5, lane = tid & 31;
    unsigned c; asm("mov.u32 %0, %%cluster_ctarank;" : "=r"(c));

    if (tid == 0) {
#pragma unroll
        for (int s = 0; s < 4; s++) mbar_init(MB_FULL(s), 1);
    }
    for (int i = tid; i < 2048; i += 512) hbuf[i] = 0.f;
    if (tid < 32) {
        qv[tid]  = gq[(int)c * DPC + tid] * rsqrtf((float)HH);
        bsn[tid] = bhh[2 * HH + (int)c * DPC + tid];
    }

    // resident rows (new layout): pass p = gate p, half h = lane>>4 -> dim 2w+h.
    // lane covers K-pairs (lane&15) + 16j, j=0..15.
    unsigned long long w[3][16];
#pragma unroll
    for (int p = 0; p < 3; p++) {
        const int grow = p * HH + (int)c * DPC + 2 * warp + (lane >> 4);
        const unsigned long long* wp = (const unsigned long long*)(whh + (size_t)grow * HH);
#pragma unroll
        for (int j = 0; j < 16; j++) w[p][j] = wp[(lane & 15) + 16 * j];
    }

    const unsigned gring_base = smem_u32(gring);
    const int pf_chunk = lane >> 3, pf_sub = lane & 7;
    const float* pf_src0 = g_gi + pf_chunk * HH + (int)c * DPC + pf_sub * 4;
    const unsigned pf_dst0 = gring_base + (unsigned)((pf_chunk * 32 + pf_sub * 4) * 4);
    const bool pf_on = (tid < 24);

    __syncthreads();
    cluster_sync_();

    const unsigned hb_base = smem_u32(hbuf);

    if (tid < 32) {
#pragma unroll
        for (int pt = 0; pt < 4; pt++) {
            if (pf_on) {
                const float* src = pf_src0 + (size_t)pt * G3;
                const unsigned dst = pf_dst0 + (unsigned)((pt & 7) * 96 * 4);
                asm volatile("cp.async.cg.shared.global [%0], [%1], 16;"
                             :: "r"(dst), "l"(src) : "memory");
            }
            asm volatile("cp.async.commit_group;" ::: "memory");
        }
    }

    for (int t = 0; t < TT; t++) {
        const int wsl = t & 3, psl = (t + 3) & 3;
        if (t > 0) mbar_wait(MB_FULL(psl), (unsigned)((t - 1) >> 2) & 1u);
        if (tid == 0) mbar_expect(MB_FULL(wsl), 2048u);

        if (tid < 32) {
            const int tn = (t + 4 < TT) ? t + 4 : TT - 1;
            if (pf_on) {
                const float* src = pf_src0 + (size_t)tn * G3;
                const unsigned dst = pf_dst0 + (unsigned)(((t + 4) & 7) * 96 * 4);
                asm volatile("cp.async.cg.shared.global [%0], [%1], 16;"
                             :: "r"(dst), "l"(src) : "memory");
            }
            asm volatile("cp.async.commit_group;" ::: "memory");
        }

        // 6 dots over h(t-1): 3 accs, 16 lanes per row
        unsigned long long acc[3];
#pragma unroll
        for (int p = 0; p < 3; p++) acc[p] = 0ull;
        const unsigned long long* h2 = (const unsigned long long*)(hbuf + psl * 512);
#pragma unroll
        for (int j = 0; j < 16; j++) {
            const unsigned long long hv = h2[(lane & 15) + 16 * j];
#pragma unroll
            for (int p = 0; p < 3; p++)
                asm("fma.rn.f32x2 %0, %1, %2, %0;" : "+l"(acc[p]) : "l"(w[p][j]), "l"(hv));
        }
        // 16-lane reduction per pass; lane (lane&15)==0 holds the row sum
#pragma unroll
        for (int p = 0; p < 3; p++) {
            float lo, hi;
            asm("mov.b64 {%0, %1}, %2;" : "=f"(lo), "=f"(hi) : "l"(acc[p]));
            float s = lo + hi;
            s += __shfl_xor_sync(0xffffffffu, s, 1);
            s += __shfl_xor_sync(0xffffffffu, s, 2);
            s += __shfl_xor_sync(0xffffffffu, s, 4);
            s += __shfl_xor_sync(0xffffffffu, s, 8);
            if ((lane & 15) == 0) ghs[p * 32 + 2 * warp + (lane >> 4)] = s;
        }
        __syncthreads();

        if (tid < 32) {
            asm volatile("cp.async.wait_group 4;" ::: "memory");
            const int m = tid;
            const float* gslot = gring + (t & 7) * 96;
            const float rg = hsig(gslot[m]      + ghs[m]);
            const float zg = hsig(gslot[32 + m] + ghs[32 + m]);
            const float ng = htanh(gslot[64 + m] + rg * (ghs[64 + m] + bsn[m]));
            const float hn = (1.f - zg) * ng + zg * hbuf[psl * 512 + (int)c * DPC + m];
            hist[t * HSTR + m] = hn;
            const unsigned dst = hb_base + (unsigned)((wsl * 512 + (int)c * DPC + m) * 4);
            const unsigned bar = MB_FULL(wsl);
#pragma unroll
            for (unsigned rk = 0; rk < CL; rk++) st_async_f32(dst, bar, rk, hn);
        }
    }
    mbar_wait(MB_FULL(3), 1u);
    __syncthreads();

    // ---- fused epilogue ----
    {
        float a = 0.f;
#pragma unroll 8
        for (int m = 0; m < 32; m++) a = fmaf(hist[tid * HSTR + m], qv[m], a);
        scp[tid] = a;
    }
    __syncthreads();
    {
        const unsigned paddr = smem_u32(part) + (unsigned)(((int)c * 512 + tid) * 4);
        st_dsmem(paddr, 0u, scp[tid]);
    }
    cluster_sync_();

    if (c == 0) {
        const float lam = fmaxf(expf(loglam[0]), 1e-4f);
        float s = 0.f;
#pragma unroll
        for (int cc = 0; cc < CL; cc++) s += part[cc * 512 + tid];
        s -= lam * (float)(TT - 1 - tid);

        float m = s;
#pragma unroll
        for (int o = 16; o > 0; o >>= 1) m = fmaxf(m, __shfl_xor_sync(0xffffffffu, m, o));
        if (lane == 0) red[warp] = m;
        __syncthreads();
        if (tid < 16) {
            float x = red[tid];
#pragma unroll
            for (int o = 8; o > 0; o >>= 1) x = fmaxf(x, __shfl_xor_sync(0xffffu, x, o));
            if (tid == 0) red[0] = x;
        }
        __syncthreads();
        const float mx = red[0];
        const float e = expf(s - mx);
        float ssum = warp_sum(e);
        __syncthreads();
        if (lane == 0) red[warp] = ssum;
        __syncthreads();
        if (tid < 16) {
            float x = red[tid];
#pragma unroll
            for (int o = 8; o > 0; o >>= 1) x += __shfl_xor_sync(0xffffu, x, o);
            if (tid == 0) red[0] = x;
        }
        __syncthreads();
        const float a = e / red[0];
        attn[tid] = a;
        if (out_size >= 1024) out[HH + tid] = a;
        const unsigned aaddr = smem_u32(attn) + (unsigned)(tid * 4);
        for (unsigned rk = 1; rk < CL; rk++) st_dsmem(aaddr, rk, a);
    }
    cluster_sync_();

    {
        const int dd = tid & 31, g = tid >> 5;
        float a = 0.f;
#pragma unroll 4
        for (int i = 0; i < 32; i++) {
            const int t = g * 32 + i;
            a = fmaf(attn[t], hist[t * HSTR + dd], a);
        }
        scp[g * 32 + dd] = a;
    }
    __syncthreads();
    if (tid < 32) {
        float s = 0.f;
#pragma unroll
        for (int g = 0; g < 16; g++) s += scp[g * 32 + tid];
        const int o = (int)c * DPC + tid;
        if (o < out_size) out[o] = s;
    }
    cluster_sync_();
}

// ---------------------------------------------------------------- launch
extern "C" void kernel_launch(void* const* d_in, const int* in_sizes, int n_in,
                              void* d_out, int out_size) {
    const int*   idx = (const int*)  d_in[0];
    const float* tf  = (const float*)d_in[1];
    const float* emb = (const float*)d_in[2];
    const float* ll  = (const float*)d_in[3];
    const float* lnw = (const float*)d_in[4];
    const float* lnb = (const float*)d_in[5];
    const float* w1  = (const float*)d_in[6];
    const float* b1  = (const float*)d_in[7];
    const float* w2  = (const float*)d_in[8];
    const float* b2  = (const float*)d_in[9];
    const float* wih = (const float*)d_in[10];
    const float* whh = (const float*)d_in[11];
    const float* bih = (const float*)d_in[12];
    const float* bhh = (const float*)d_in[13];
    const float* q   = (const float*)d_in[14];
    const float* llm = (const float*)d_in[15];
    float* out = (float*)d_out;

    const int k3_smem = 29120 * (int)sizeof(float);   // 116480 B

    static int attr_done = 0;
    if (!attr_done) {
        cudaFuncSetAttribute(k3_gru, cudaFuncAttributeNonPortableClusterSizeAllowed, 1);
        cudaFuncSetAttribute(k3_gru, cudaFuncAttributeMaxDynamicSharedMemorySize, k3_smem);
        attr_done = 1;
    }

    k1a<<<dim3(64, 2), 256>>>(idx, tf, emb, ll, lnw, lnb, w1, b1);
    k1b<<<dim3(64, 2), 256>>>(w2, b2);
    k2_gi<<<dim3(32, 6), 256>>>(wih, bih, bhh);
    k3_gru<<<CL, 512, k3_smem>>>(whh, bhh, q, llm, out, out_size);
}